// round 1
// baseline (speedup 1.0000x reference)
#include <cuda_runtime.h>

#define NB 2
#define CD 256
#define LL 4096
#define NH 4
#define DKH 64

static constexpr float LOG2E = 1.4426950408889634f;

// Scratch (device globals; no allocations allowed)
__device__ float g_x[NB * LL * CD];        // x transposed: [b][l][c]
__device__ float g_q[NB * NH * LL * DKH];  // qkv heads:    [b][h][l][d]
__device__ float g_att[NB * LL * CD];      // attn out:     [b][l][h*64+d]
__device__ float g_y[NB * LL * CD];        // fc+residual:  [b][l][c]

// ---------------------------------------------------------------------------
// Kernel 1: QKV projection + write transposed x.
// out[l,o] = sum_c x_in[b][c][l] * W[o][c]     (x_in is the [B,C,H,W] input)
// Tile 64(l) x 64(o), k-chunks of 64. 256 threads, 4x4 microtile per thread.
// ---------------------------------------------------------------------------
__global__ __launch_bounds__(256) void k_qkv(const float* __restrict__ qin,
                                             const float* __restrict__ wqkv) {
    __shared__ float As[64][68];  // As[c][l]
    __shared__ float Ws[64][68];  // Ws[c][o]
    const int bt = blockIdx.z;
    const int o0 = blockIdx.y * 64;
    const int l0 = blockIdx.x * 64;
    const int tid = threadIdx.x;
    const int tx = tid & 15, ty = tid >> 4;

    float acc[4][4] = {};
    for (int c0 = 0; c0 < CD; c0 += 64) {
        __syncthreads();
        #pragma unroll
        for (int idx = tid; idx < 64 * 64; idx += 256) {
            int ci = idx >> 6, lj = idx & 63;
            As[ci][lj] = qin[bt * CD * LL + (c0 + ci) * LL + l0 + lj];
        }
        #pragma unroll
        for (int idx = tid; idx < 64 * 64; idx += 256) {
            int oi = idx >> 6, cj = idx & 63;
            Ws[cj][oi] = wqkv[(o0 + oi) * CD + c0 + cj];
        }
        __syncthreads();
        if (blockIdx.y == 0) {
            // write x transposed for the residual path
            #pragma unroll
            for (int idx = tid; idx < 64 * 64; idx += 256) {
                int li = idx >> 6, cj = idx & 63;
                g_x[(bt * LL + l0 + li) * CD + c0 + cj] = As[cj][li];
            }
        }
        #pragma unroll 8
        for (int c = 0; c < 64; c++) {
            float4 a = *(const float4*)&As[c][ty * 4];
            float4 w = *(const float4*)&Ws[c][tx * 4];
            float av[4] = {a.x, a.y, a.z, a.w};
            float wv[4] = {w.x, w.y, w.z, w.w};
            #pragma unroll
            for (int i = 0; i < 4; i++)
                #pragma unroll
                for (int j = 0; j < 4; j++) acc[i][j] += av[i] * wv[j];
        }
    }
    const int h = blockIdx.y;  // o-tile == head (64 wide each)
    #pragma unroll
    for (int i = 0; i < 4; i++) {
        float4 v = make_float4(acc[i][0], acc[i][1], acc[i][2], acc[i][3]);
        *(float4*)&g_q[((bt * NH + h) * LL + l0 + ty * 4 + i) * DKH + tx * 4] = v;
    }
}

// ---------------------------------------------------------------------------
// Kernel 2: flash attention (fp32). Q == K == V (shared projection).
// Per CTA: one (b,h), 64 query rows. Loop over 64 key tiles of 64.
// smem: Qt[d][m], Kt[d][n] (transposed for float4 operand loads),
//       Vs[n][v], Ps[m][n]. 4 x 64 x 68 floats = 68 KB -> dynamic smem.
// ---------------------------------------------------------------------------
extern __shared__ float sm_attn[];
__global__ __launch_bounds__(256, 2) void k_attn() {
    float* Qt = sm_attn;               // [64][68]
    float* Kt = sm_attn + 64 * 68;     // [64][68]
    float* Vs = sm_attn + 2 * 64 * 68; // [64][68]
    float* Ps = sm_attn + 3 * 64 * 68; // [64][68]

    const int bh = blockIdx.y;                    // b*NH + h
    const float* qb = g_q + bh * LL * DKH;
    const int m0 = blockIdx.x * 64;
    const int tid = threadIdx.x;
    const int tx = tid & 15, ty = tid >> 4;

    // load Q tile transposed (once)
    for (int idx = tid; idx < 64 * 64; idx += 256) {
        int m = idx >> 6, d = idx & 63;
        Qt[d * 68 + m] = qb[(m0 + m) * DKH + d];
    }

    float O[4][4] = {};
    float mr[4], lr[4];
    #pragma unroll
    for (int i = 0; i < 4; i++) { mr[i] = -1e30f; lr[i] = 0.f; }

    for (int n0 = 0; n0 < LL; n0 += 64) {
        __syncthreads();
        // K tile == V tile (same data, two smem layouts)
        for (int idx = tid; idx < 64 * 64; idx += 256) {
            int n = idx >> 6, d = idx & 63;
            float v = qb[(n0 + n) * DKH + d];
            Kt[d * 68 + n] = v;
            Vs[n * 68 + d] = v;
        }
        __syncthreads();

        // S = Q K^T (4x4 microtile per thread)
        float s[4][4] = {};
        #pragma unroll 4
        for (int d = 0; d < 64; d++) {
            float4 a = *(const float4*)&Qt[d * 68 + ty * 4];
            float4 b = *(const float4*)&Kt[d * 68 + tx * 4];
            float av[4] = {a.x, a.y, a.z, a.w};
            float bv[4] = {b.x, b.y, b.z, b.w};
            #pragma unroll
            for (int i = 0; i < 4; i++)
                #pragma unroll
                for (int j = 0; j < 4; j++) s[i][j] += av[i] * bv[j];
        }

        // online softmax per row (reduce across the 16 tx lanes)
        #pragma unroll
        for (int i = 0; i < 4; i++) {
            #pragma unroll
            for (int j = 0; j < 4; j++) s[i][j] *= 0.125f;  // 1/sqrt(64)
            float mx = fmaxf(fmaxf(s[i][0], s[i][1]), fmaxf(s[i][2], s[i][3]));
            #pragma unroll
            for (int off = 1; off < 16; off <<= 1)
                mx = fmaxf(mx, __shfl_xor_sync(0xffffffffu, mx, off));
            float mnew = fmaxf(mr[i], mx);
            float corr = exp2f((mr[i] - mnew) * LOG2E);
            float p[4]; float rs = 0.f;
            #pragma unroll
            for (int j = 0; j < 4; j++) {
                p[j] = exp2f((s[i][j] - mnew) * LOG2E);
                rs += p[j];
            }
            #pragma unroll
            for (int off = 1; off < 16; off <<= 1)
                rs += __shfl_xor_sync(0xffffffffu, rs, off);
            lr[i] = lr[i] * corr + rs;
            mr[i] = mnew;
            #pragma unroll
            for (int j = 0; j < 4; j++) O[i][j] *= corr;
            *(float4*)&Ps[(ty * 4 + i) * 68 + tx * 4] =
                make_float4(p[0], p[1], p[2], p[3]);
        }
        __syncthreads();

        // O += P @ V
        #pragma unroll 4
        for (int n = 0; n < 64; n++) {
            float4 b = *(const float4*)&Vs[n * 68 + tx * 4];
            float bv[4] = {b.x, b.y, b.z, b.w};
            #pragma unroll
            for (int i = 0; i < 4; i++) {
                float a = Ps[(ty * 4 + i) * 68 + n];
                #pragma unroll
                for (int j = 0; j < 4; j++) O[i][j] += a * bv[j];
            }
        }
    }

    const int b = bh >> 2, h = bh & 3;
    #pragma unroll
    for (int i = 0; i < 4; i++) {
        float inv = 1.0f / lr[i];
        float4 o = make_float4(O[i][0] * inv, O[i][1] * inv,
                               O[i][2] * inv, O[i][3] * inv);
        *(float4*)&g_att[(b * LL + m0 + ty * 4 + i) * CD + h * DKH + tx * 4] = o;
    }
}

// ---------------------------------------------------------------------------
// Kernel 3: fc GEMM + bias + residual.  y[r,o] = att[r,:] . fc_w[o,:] + b + x
// ---------------------------------------------------------------------------
__global__ __launch_bounds__(256) void k_fc(const float* __restrict__ fw,
                                            const float* __restrict__ fb) {
    __shared__ float At[64][68];  // At[k][r]
    __shared__ float Ws[64][68];  // Ws[k][o]
    const int r0 = blockIdx.x * 64;   // row in [0, B*L)
    const int o0 = blockIdx.y * 64;
    const int tid = threadIdx.x;
    const int tx = tid & 15, ty = tid >> 4;

    float acc[4][4] = {};
    for (int k0 = 0; k0 < CD; k0 += 64) {
        __syncthreads();
        #pragma unroll
        for (int idx = tid; idx < 64 * 64; idx += 256) {
            int ri = idx >> 6, kj = idx & 63;
            At[kj][ri] = g_att[(r0 + ri) * CD + k0 + kj];
        }
        #pragma unroll
        for (int idx = tid; idx < 64 * 64; idx += 256) {
            int oi = idx >> 6, kj = idx & 63;
            Ws[kj][oi] = fw[(o0 + oi) * CD + k0 + kj];
        }
        __syncthreads();
        #pragma unroll 8
        for (int k = 0; k < 64; k++) {
            float4 a = *(const float4*)&At[k][ty * 4];
            float4 w = *(const float4*)&Ws[k][tx * 4];
            float av[4] = {a.x, a.y, a.z, a.w};
            float wv[4] = {w.x, w.y, w.z, w.w};
            #pragma unroll
            for (int i = 0; i < 4; i++)
                #pragma unroll
                for (int j = 0; j < 4; j++) acc[i][j] += av[i] * wv[j];
        }
    }
    #pragma unroll
    for (int i = 0; i < 4; i++) {
        int r = r0 + ty * 4 + i;
        float4 bias = *(const float4*)&fb[o0 + tx * 4];
        float4 res  = *(const float4*)&g_x[r * CD + o0 + tx * 4];
        float4 v = make_float4(acc[i][0] + bias.x + res.x,
                               acc[i][1] + bias.y + res.y,
                               acc[i][2] + bias.z + res.z,
                               acc[i][3] + bias.w + res.w);
        *(float4*)&g_y[r * CD + o0 + tx * 4] = v;
    }
}

// ---------------------------------------------------------------------------
// Kernel 4: LayerNorm over C=256. One warp per row, 8 rows per block.
// ---------------------------------------------------------------------------
__global__ __launch_bounds__(256) void k_ln(const float* __restrict__ gam,
                                            const float* __restrict__ bet,
                                            float* __restrict__ out) {
    const int row = blockIdx.x * 8 + (threadIdx.x >> 5);
    const int lane = threadIdx.x & 31;
    const float* y = g_y + row * CD;
    float v[8], s = 0.f, s2 = 0.f;
    #pragma unroll
    for (int k = 0; k < 8; k++) {
        v[k] = y[lane + 32 * k];
        s += v[k];
        s2 += v[k] * v[k];
    }
    #pragma unroll
    for (int off = 16; off; off >>= 1) {
        s  += __shfl_xor_sync(0xffffffffu, s, off);
        s2 += __shfl_xor_sync(0xffffffffu, s2, off);
    }
    const float mu = s * (1.f / CD);
    const float rstd = rsqrtf(s2 * (1.f / CD) - mu * mu + 1e-5f);
    #pragma unroll
    for (int k = 0; k < 8; k++) {
        int c = lane + 32 * k;
        out[row * CD + c] = (v[k] - mu) * rstd * gam[c] + bet[c];
    }
}

// ---------------------------------------------------------------------------
extern "C" void kernel_launch(void* const* d_in, const int* in_sizes, int n_in,
                              void* d_out, int out_size) {
    const float* qin = (const float*)d_in[0];
    const float* wq  = (const float*)d_in[1];
    const float* fw  = (const float*)d_in[2];
    const float* fb  = (const float*)d_in[3];
    const float* lg  = (const float*)d_in[4];
    const float* lb  = (const float*)d_in[5];
    float* out = (float*)d_out;

    const int attn_smem = 4 * 64 * 68 * (int)sizeof(float);  // 69,632 B
    cudaFuncSetAttribute(k_attn, cudaFuncAttributeMaxDynamicSharedMemorySize,
                         attn_smem);

    k_qkv<<<dim3(LL / 64, NH, NB), 256>>>(qin, wq);
    k_attn<<<dim3(LL / 64, NB * NH), 256, attn_smem>>>();
    k_fc<<<dim3(NB * LL / 64, CD / 64), 256>>>(fw, fb);
    k_ln<<<NB * LL / 8, 256>>>(lg, lb, out);
}